// round 14
// baseline (speedup 1.0000x reference)
#include <cuda_runtime.h>
#include <cuda_fp16.h>
#include <math.h>
#include <stdint.h>

typedef uint32_t u32;
typedef uint64_t u64;

#define OUTSZ (2048u*12u*20u*64u)

// ---------------- static device scratch (fp16, position-major m' = p*2048 + b) ----------------
__device__ __align__(256) __half g_xh  [40960u*768u];   // X reordered [p][b][768]
__device__ __align__(256) __half g_w1h [384u*768u];
__device__ __align__(256) __half g_wqh [768u*768u];
__device__ __align__(256) __half g_wkh [768u*768u];
__device__ __align__(256) __half g_wvh [768u*768u];
__device__ __align__(256) __half g_w2th[768u*3456u];    // w2 -> [o][tap*384+i]
__device__ __align__(256) __half g_t1h [40960u*384u];   // gelu(conv1x1), [p][b][384]
__device__ __align__(256) __half g_t2h [40960u*768u];   // gelu(conv3x3) out, [p][b][768]
__device__ __align__(256) __half g_fh  [8192u*768u];    // filtered rows, [b*4+y][768]

// ---------------- helpers ----------------
__device__ __forceinline__ u32 smem_u32(const void* p) {
    u32 a;
    asm("{ .reg .u64 t; cvta.to.shared.u64 t, %1; cvt.u32.u64 %0, t; }" : "=r"(a) : "l"(p));
    return a;
}
__device__ __forceinline__ float gelu_f(float v) {
    return 0.5f * v * (1.0f + erff(v * 0.7071067811865476f));
}

#define CPA(sa, ga, sz) asm volatile("cp.async.cg.shared.global [%0], [%1], 16, %2;" :: "r"(sa), "l"(ga), "r"(sz) : "memory")
#define CPC()  asm volatile("cp.async.commit_group;" ::: "memory")
#define CPW(n) asm volatile("cp.async.wait_group %0;" :: "n"(n) : "memory")

__device__ __forceinline__ void mma16(float* c, const u32* a, const u32* b) {
    asm volatile("mma.sync.aligned.m16n8k16.row.col.f32.f16.f16.f32 "
        "{%0,%1,%2,%3}, {%4,%5,%6,%7}, {%8,%9}, {%0,%1,%2,%3};"
        : "+f"(c[0]), "+f"(c[1]), "+f"(c[2]), "+f"(c[3])
        : "r"(a[0]), "r"(a[1]), "r"(a[2]), "r"(a[3]), "r"(b[0]), "r"(b[1]));
}
__device__ __forceinline__ void ldmx4(u32& r0, u32& r1, u32& r2, u32& r3, u32 addr) {
    asm volatile("ldmatrix.sync.aligned.m8n8.x4.shared.b16 {%0,%1,%2,%3}, [%4];"
                 : "=r"(r0), "=r"(r1), "=r"(r2), "=r"(r3) : "r"(addr));
}
__device__ __forceinline__ uint4 pack8h(float4 a, float4 b) {
    __half2 h0 = __floats2half2_rn(a.x, a.y), h1 = __floats2half2_rn(a.z, a.w);
    __half2 h2 = __floats2half2_rn(b.x, b.y), h3 = __floats2half2_rn(b.z, b.w);
    uint4 u;
    u.x = *(const unsigned*)&h0; u.y = *(const unsigned*)&h1;
    u.z = *(const unsigned*)&h2; u.w = *(const unsigned*)&h3;
    return u;
}

// ---------------- prep 1: X reorder (launch #1) ----------------
__global__ void kprepX(const float* __restrict__ X) {
    int idx = blockIdx.x * 256 + threadIdx.x;     // over 40960*96 8-float granules
    if (idx >= 40960 * 96) return;
    int mp = idx / 96, c = idx - mp * 96;
    int p = mp >> 11, b = mp & 2047;
    const float* src = X + ((size_t)b * 21 + 1 + p) * 768 + c * 8;
    float4 a = *(const float4*)src, bb = *(const float4*)(src + 4);
    *(uint4*)(g_xh + (size_t)mp * 768 + c * 8) = pack8h(a, bb);
}

// ---------------- prep 2: weights + smem-tiled w2 transpose (launch #2) ----------------
#define WG1  36864                // w1 granules  (384*768/8)
#define WGQ  73728                // per q/k/v    (768*768/8)
#define WB   1008                 // (36864+3*73728)/256 blocks
__global__ void kprepW(const float* __restrict__ w1, const float* __restrict__ wq,
                       const float* __restrict__ wk, const float* __restrict__ wv,
                       const float* __restrict__ w2) {
    __shared__ __half s[4 * 3456];
    int blk = blockIdx.x;
    if (blk < WB) {
        int idx = blk * 256 + threadIdx.x;
        const float* src; __half* dst; int i;
        if (idx < WG1)                   { i = idx;                src = w1; dst = g_w1h; }
        else if (idx < WG1 + WGQ)        { i = idx - WG1;          src = wq; dst = g_wqh; }
        else if (idx < WG1 + 2 * WGQ)    { i = idx - WG1 - WGQ;    src = wk; dst = g_wkh; }
        else                             { i = idx - WG1 - 2*WGQ;  src = wv; dst = g_wvh; }
        float4 a = *(const float4*)(src + (size_t)i * 8);
        float4 b = *(const float4*)(src + (size_t)i * 8 + 4);
        *(uint4*)(dst + (size_t)i * 8) = pack8h(a, b);
    } else {
        int o0 = (blk - WB) * 4;
        for (int e = threadIdx.x; e < 4 * 3456; e += 256) {
            int ol = e / 3456, j = e - ol * 3456;
            s[ol * 3456 + j] = __float2half(w2[(size_t)(o0 + ol) * 3456 + j]);
        }
        __syncthreads();
        for (int e = threadIdx.x; e < 4 * 3456; e += 256) {
            int ol = e / 3456, d = e - ol * 3456;
            int ic = d % 384, t = d / 384;
            g_w2th[(size_t)(o0 + ol) * 3456 + d] = s[ol * 3456 + ic * 9 + t];
        }
    }
}

// =====================================================================
// generic GEMM: BM=256, BN=128, BK=32, 3-stage, 16 warps (512 thr),
// warp grid 4(M)x4(N), warp tile 64x32, 1 CTA/SM (full regfile)
// =====================================================================
#define LDSH 40
#define ASMH (256 * LDSH)
#define BSMH (128 * LDSH)
#define STGH (ASMH + BSMH)
#define SMEMB (3 * STGH * 2)      // 92160 bytes

template<int MODE>
__global__ __launch_bounds__(512, 1) void gemm_h(float* __restrict__ Cout) {
    constexpr int L = 24;
    extern __shared__ __half smh[];
    const u32 sbase = smem_u32(smh);
    const int tid = threadIdx.x, wid = tid >> 5, lane = tid & 31;
    const int wm = wid >> 2, wn = wid & 3;
    const int lr = lane >> 2, lc = lane & 3;
    const int n0 = blockIdx.x * 128, m0 = blockIdx.y * 256;

    int which = 0, nw0 = n0;
    const __half* Bb;
    if (MODE == 2) {
        which = n0 / 768; nw0 = n0 - which * 768;
        Bb = (which == 0) ? g_wqh : (which == 1) ? g_wkh : g_wvh;
    } else {
        Bb = g_w1h;
    }
    const __half* Ab = (MODE == 0) ? g_xh : g_fh;

    const int arow_t = wm * 64 + ((lane >> 3) & 1) * 8 + (lane & 7);
    const int acol_t = (lane >> 4) * 8;
    const int brow_t = wn * 32 + (lane >> 4) * 8 + (lane & 7);
    const int bcol_t = ((lane >> 3) & 1) * 8;

    // A: 256x32 fp16 = 1024 16B slots -> 2/thread; B: 128x32 = 512 -> 1/thread
    u32 saoff[2]; const __half* aptr[2];
#pragma unroll
    for (int v = 0; v < 2; v++) {
        int idx = v * 512 + tid, r = idx >> 2, c4 = idx & 3;
        saoff[v] = (u32)(r * LDSH + c4 * 8) * 2u;
        aptr[v] = Ab + (size_t)(m0 + r) * 768 + c4 * 8;
    }
    u32 sboff; const __half* bptr;
    {
        int r = tid >> 2, c4 = tid & 3;
        sboff = (u32)(ASMH + r * LDSH + c4 * 8) * 2u;
        bptr = Bb + (size_t)(nw0 + r) * 768 + c4 * 8;
    }

    auto load = [&](int c, int s) {
        u32 base = sbase + (u32)(s * STGH) * 2u;
#pragma unroll
        for (int v = 0; v < 2; v++) CPA(base + saoff[v], aptr[v] + (size_t)c * 32, 16u);
        CPA(base + sboff, bptr + (size_t)c * 32, 16u);
        CPC();
    };

    float acc[4][4][4];
#pragma unroll
    for (int i = 0; i < 4; i++)
#pragma unroll
        for (int j = 0; j < 4; j++)
#pragma unroll
            for (int q = 0; q < 4; q++) acc[i][j][q] = 0.f;

    load(0, 0);
    load(1, 1);

    for (int c = 0; c < L; c++) {
        int s = c % 3;
        CPW(1);
        __syncthreads();
        if (c + 2 < L) load(c + 2, (c + 2) % 3); else CPC();

        const u32 sA = sbase + (u32)(s * STGH) * 2u;
        const u32 sB = sA + (u32)ASMH * 2u;
#pragma unroll
        for (int ks = 0; ks < 2; ks++) {
            u32 af[4][4];
#pragma unroll
            for (int mt = 0; mt < 4; mt++) {
                u32 addr = sA + (u32)((arow_t + mt * 16) * LDSH + acol_t + ks * 16) * 2u;
                ldmx4(af[mt][0], af[mt][1], af[mt][2], af[mt][3], addr);
            }
            u32 bf[4][2];
#pragma unroll
            for (int np = 0; np < 2; np++) {
                u32 addr = sB + (u32)((brow_t + np * 16) * LDSH + bcol_t + ks * 16) * 2u;
                ldmx4(bf[np * 2][0], bf[np * 2][1], bf[np * 2 + 1][0], bf[np * 2 + 1][1], addr);
            }
#pragma unroll
            for (int mt = 0; mt < 4; mt++)
#pragma unroll
                for (int nt = 0; nt < 4; nt++)
                    mma16(acc[mt][nt], af[mt], bf[nt]);
        }
    }

#pragma unroll
    for (int mt = 0; mt < 4; mt++) {
        int r0 = m0 + wm * 64 + mt * 16 + lr;
#pragma unroll
        for (int half = 0; half < 2; half++) {
            int m = r0 + half * 8;
#pragma unroll
            for (int nt = 0; nt < 4; nt++) {
                float v0 = acc[mt][nt][half * 2 + 0];
                float v1 = acc[mt][nt][half * 2 + 1];
                int colL = wn * 32 + nt * 8 + lc * 2;
                if (MODE == 0) {
                    __half2 h = __floats2half2_rn(gelu_f(v0), gelu_f(v1));
                    *(__half2*)(g_t1h + (size_t)m * 384 + n0 + colL) = h;
                } else {
                    int b = m >> 2, y = m & 3;
                    int n = nw0 + colL, nh = n >> 6, d = n & 63;
                    float* bp = Cout + (size_t)which * OUTSZ
                              + (((size_t)b * 12 + nh) * 20 + y * 5) * 64 + d;
                    float2 v = make_float2(v0, v1);
#pragma unroll
                    for (int xx = 0; xx < 5; xx++) *(float2*)(bp + xx * 64) = v;
                }
            }
        }
    }
}

// =====================================================================
// conv GEMM: BM=256, BN=128, BK=64, 3-stage (166KB smem, 1 CTA/SM),
// 16 warps, warp grid 4x4, single position per CTA, valid taps only
// =====================================================================
#define LDK  72
#define AS2  (256 * LDK)
#define BS2  (128 * LDK)
#define ST2  (AS2 + BS2)
#define SMEMC (3 * ST2 * 2)       // 165888 bytes

__global__ __launch_bounds__(512, 1) void gemm_conv() {
    extern __shared__ __half smh[];
    const u32 sbase = smem_u32(smh);
    const int tid = threadIdx.x, wid = tid >> 5, lane = tid & 31;
    const int wm = wid >> 2, wn = wid & 3;
    const int lr = lane >> 2, lc = lane & 3;
    const int n0 = blockIdx.x * 128;
    // wave-balanced m-tile remap: consecutive y span all 20 positions
    const int p = blockIdx.y % 20, bt = blockIdx.y / 20;   // bt: 0..7 (256 batches)
    const int m0 = p * 2048 + bt * 256;
    const int py = p / 5, px = p - py * 5;

    // bit-packed valid-tap tables
    u64 spack = 0, wpack = 0; int ntap = 0;
#pragma unroll
    for (int dy = -1; dy <= 1; dy++) {
        int ny = py + dy; if ((unsigned)ny >= 4u) continue;
#pragma unroll
        for (int dx = -1; dx <= 1; dx++) {
            int nx = px + dx; if ((unsigned)nx >= 5u) continue;
            spack |= (u64)(ny * 5 + nx) << (5 * ntap);
            wpack |= (u64)((dy + 1) * 3 + (dx + 1)) << (4 * ntap);
            ntap++;
        }
    }
    const int L = ntap * 6;                       // 384/64 chunks per tap

    const int arow_t = wm * 64 + ((lane >> 3) & 1) * 8 + (lane & 7);
    const int acol_t = (lane >> 4) * 8;
    const int brow_t = wn * 32 + (lane >> 4) * 8 + (lane & 7);
    const int bcol_t = ((lane >> 3) & 1) * 8;

    // A: 256x64 fp16 = 2048 slots -> 4/thread; B: 128x64 = 1024 -> 2/thread
    u32 saoff[4]; int aoff[4];
    u32 sboff[2]; const __half* bptr[2];
#pragma unroll
    for (int v = 0; v < 4; v++) {
        int idx = v * 512 + tid, r = idx >> 3, c8 = idx & 7;   // r: 0..255
        saoff[v] = (u32)(r * LDK + c8 * 8) * 2u;
        aoff[v] = (bt * 256 + r) * 384 + c8 * 8;
    }
#pragma unroll
    for (int v = 0; v < 2; v++) {
        int idx = v * 512 + tid, r = idx >> 3, c8 = idx & 7;   // r: 0..127
        sboff[v] = (u32)(AS2 + r * LDK + c8 * 8) * 2u;
        bptr[v] = g_w2th + (size_t)(n0 + r) * 3456 + c8 * 8;
    }

    auto load = [&](int c, int s) {
        int ti = c / 6, cc = c - ti * 6, kk = cc * 64;
        int srcp = (int)((spack >> (5 * ti)) & 31u);
        int wt   = (int)((wpack >> (4 * ti)) & 15u);
        const __half* Asl = g_t1h + (size_t)srcp * (2048u * 384u) + kk;
        int boff = wt * 384 + kk;
        u32 base = sbase + (u32)(s * ST2) * 2u;
#pragma unroll
        for (int v = 0; v < 4; v++) CPA(base + saoff[v], Asl + aoff[v], 16u);
#pragma unroll
        for (int v = 0; v < 2; v++) CPA(base + sboff[v], bptr[v] + boff, 16u);
        CPC();
    };

    float acc[4][4][4];
#pragma unroll
    for (int i = 0; i < 4; i++)
#pragma unroll
        for (int j = 0; j < 4; j++)
#pragma unroll
            for (int q = 0; q < 4; q++) acc[i][j][q] = 0.f;

    load(0, 0);
    load(1, 1);

    for (int c = 0; c < L; c++) {
        int s = c % 3;
        CPW(1);
        __syncthreads();
        if (c + 2 < L) load(c + 2, (c + 2) % 3); else CPC();

        const u32 sA = sbase + (u32)(s * ST2) * 2u;
        const u32 sB = sA + (u32)AS2 * 2u;
#pragma unroll
        for (int ks = 0; ks < 4; ks++) {
            u32 af[4][4];
#pragma unroll
            for (int mt = 0; mt < 4; mt++) {
                u32 addr = sA + (u32)((arow_t + mt * 16) * LDK + acol_t + ks * 16) * 2u;
                ldmx4(af[mt][0], af[mt][1], af[mt][2], af[mt][3], addr);
            }
            u32 bf[4][2];
#pragma unroll
            for (int np = 0; np < 2; np++) {
                u32 addr = sB + (u32)((brow_t + np * 16) * LDK + bcol_t + ks * 16) * 2u;
                ldmx4(bf[np * 2][0], bf[np * 2][1], bf[np * 2 + 1][0], bf[np * 2 + 1][1], addr);
            }
#pragma unroll
            for (int mt = 0; mt < 4; mt++)
#pragma unroll
                for (int nt = 0; nt < 4; nt++)
                    mma16(acc[mt][nt], af[mt], bf[nt]);
        }
    }

    // epilogue: gelu fused (kfilter is pure bandwidth)
#pragma unroll
    for (int mt = 0; mt < 4; mt++) {
        int r0 = m0 + wm * 64 + mt * 16 + lr;
#pragma unroll
        for (int half = 0; half < 2; half++) {
            int m = r0 + half * 8;
#pragma unroll
            for (int nt = 0; nt < 4; nt++) {
                float v0 = gelu_f(acc[mt][nt][half * 2 + 0]);
                float v1 = gelu_f(acc[mt][nt][half * 2 + 1]);
                int colL = wn * 32 + nt * 8 + lc * 2;
                __half2 h = __floats2half2_rn(v0, v1);
                *(__half2*)(g_t2h + (size_t)m * 768 + n0 + colL) = h;
            }
        }
    }
}

// ---------------- filter (launch #5): pure-bandwidth sums + analytic low-pass ----------------
__global__ void kfilter() {
    int idx = blockIdx.x * 256 + threadIdx.x;     // over 2048*192 (4 channels each)
    if (idx >= 2048 * 192) return;
    int b = idx / 192, oq = idx - b * 192;
    const __half* src = g_t2h + (size_t)b * 768 + oq * 4;
    float ry[4][4];
#pragma unroll
    for (int y = 0; y < 4; y++) {
        float a0 = 0.f, a1 = 0.f, a2 = 0.f, a3 = 0.f;
#pragma unroll
        for (int x = 0; x < 5; x++) {
            const __half2* pp = (const __half2*)(src + (size_t)(y * 5 + x) * 2048u * 768u);
            float2 v01 = __half22float2(pp[0]);
            float2 v23 = __half22float2(pp[1]);
            a0 += v01.x; a1 += v01.y; a2 += v23.x; a3 += v23.y;
        }
        ry[y][0] = a0; ry[y][1] = a1; ry[y][2] = a2; ry[y][3] = a3;
    }
    __half o[4][4];
#pragma unroll
    for (int j = 0; j < 4; j++) {
        float S  = ry[0][j] + ry[1][j] + ry[2][j] + ry[3][j];
        float A  = ry[0][j] - ry[2][j];
        float Bv = ry[1][j] - ry[3][j];
        o[0][j] = __float2half(sqrtf((S + A) * (S + A) + Bv * Bv) * 0.05f);
        o[1][j] = __float2half(sqrtf((S + Bv) * (S + Bv) + A * A) * 0.05f);
        o[2][j] = __float2half(sqrtf((S - A) * (S - A) + Bv * Bv) * 0.05f);
        o[3][j] = __float2half(sqrtf((S - Bv) * (S - Bv) + A * A) * 0.05f);
    }
    __half* dst = g_fh + (size_t)b * 4 * 768 + oq * 4;
#pragma unroll
    for (int y = 0; y < 4; y++) {
        uint2 u;
        __half2 h0; h0.x = o[y][0]; h0.y = o[y][1];
        __half2 h1; h1.x = o[y][2]; h1.y = o[y][3];
        u.x = *(const unsigned*)&h0; u.y = *(const unsigned*)&h1;
        *(uint2*)(dst + (size_t)y * 768) = u;
    }
}

// ---------------- launch ----------------
extern "C" void kernel_launch(void* const* d_in, const int* in_sizes, int n_in,
                              void* d_out, int out_size) {
    const float* x  = (const float*)d_in[0];
    const float* w1 = (const float*)d_in[1];
    const float* w2 = (const float*)d_in[2];
    const float* wq = (const float*)d_in[3];
    const float* wk = (const float*)d_in[4];
    const float* wv = (const float*)d_in[5];
    float* out = (float*)d_out;

    cudaFuncSetAttribute(gemm_h<0>, cudaFuncAttributeMaxDynamicSharedMemorySize, SMEMB);
    cudaFuncSetAttribute(gemm_h<2>, cudaFuncAttributeMaxDynamicSharedMemorySize, SMEMB);
    cudaFuncSetAttribute(gemm_conv, cudaFuncAttributeMaxDynamicSharedMemorySize, SMEMC);

    kprepX<<<15360, 256>>>(x);                                // #1: X reorder
    kprepW<<<WB + 192, 256>>>(w1, wq, wk, wv, w2);            // #2: weights + w2t transpose
    gemm_h<0><<<dim3(3, 160), 512, SMEMB>>>(nullptr);         // #3: t1 = gelu(X@W1^T)
    gemm_conv<<<dim3(6, 160), 512, SMEMC>>>();                // #4: conv3x3 + gelu (ncu target)
    kfilter<<<(2048 * 192 + 255) / 256, 256>>>();             // #5: sums + analytic low-pass
    gemm_h<2><<<dim3(18, 32), 512, SMEMB>>>(out);             // #6: QKV + replicated scatter
}

// round 15
// speedup vs baseline: 1.0650x; 1.0650x over previous
#include <cuda_runtime.h>
#include <cuda_fp16.h>
#include <math.h>
#include <stdint.h>

typedef uint32_t u32;
typedef uint64_t u64;

#define OUTSZ (2048u*12u*20u*64u)

// ---------------- static device scratch (fp16, position-major m' = p*2048 + b) ----------------
__device__ __align__(256) __half g_xh  [40960u*768u];   // X reordered [p][b][768]
__device__ __align__(256) __half g_w1h [384u*768u];
__device__ __align__(256) __half g_wqh [768u*768u];
__device__ __align__(256) __half g_wkh [768u*768u];
__device__ __align__(256) __half g_wvh [768u*768u];
__device__ __align__(256) __half g_w2th[768u*3456u];    // w2 -> [o][tap*384+i]
__device__ __align__(256) __half g_t1h [40960u*384u];   // gelu(conv1x1), [p][b][384]
__device__ __align__(256) __half g_t2h [40960u*768u];   // gelu(conv3x3) out, [p][b][768]
__device__ __align__(256) __half g_fh  [8192u*768u];    // filtered rows, [b*4+y][768]

// ---------------- helpers ----------------
__device__ __forceinline__ u32 smem_u32(const void* p) {
    u32 a;
    asm("{ .reg .u64 t; cvta.to.shared.u64 t, %1; cvt.u32.u64 %0, t; }" : "=r"(a) : "l"(p));
    return a;
}
__device__ __forceinline__ float gelu_f(float v) {
    return 0.5f * v * (1.0f + erff(v * 0.7071067811865476f));
}

#define CPA(sa, ga, sz) asm volatile("cp.async.cg.shared.global [%0], [%1], 16, %2;" :: "r"(sa), "l"(ga), "r"(sz) : "memory")
#define CPC()  asm volatile("cp.async.commit_group;" ::: "memory")
#define CPW(n) asm volatile("cp.async.wait_group %0;" :: "n"(n) : "memory")

__device__ __forceinline__ void mma16(float* c, const u32* a, const u32* b) {
    asm volatile("mma.sync.aligned.m16n8k16.row.col.f32.f16.f16.f32 "
        "{%0,%1,%2,%3}, {%4,%5,%6,%7}, {%8,%9}, {%0,%1,%2,%3};"
        : "+f"(c[0]), "+f"(c[1]), "+f"(c[2]), "+f"(c[3])
        : "r"(a[0]), "r"(a[1]), "r"(a[2]), "r"(a[3]), "r"(b[0]), "r"(b[1]));
}
__device__ __forceinline__ void ldmx4(u32& r0, u32& r1, u32& r2, u32& r3, u32 addr) {
    asm volatile("ldmatrix.sync.aligned.m8n8.x4.shared.b16 {%0,%1,%2,%3}, [%4];"
                 : "=r"(r0), "=r"(r1), "=r"(r2), "=r"(r3) : "r"(addr));
}
__device__ __forceinline__ uint4 pack8h(float4 a, float4 b) {
    __half2 h0 = __floats2half2_rn(a.x, a.y), h1 = __floats2half2_rn(a.z, a.w);
    __half2 h2 = __floats2half2_rn(b.x, b.y), h3 = __floats2half2_rn(b.z, b.w);
    uint4 u;
    u.x = *(const unsigned*)&h0; u.y = *(const unsigned*)&h1;
    u.z = *(const unsigned*)&h2; u.w = *(const unsigned*)&h3;
    return u;
}

// ---------------- prep 1: X reorder (launch #1) ----------------
__global__ void kprepX(const float* __restrict__ X) {
    int idx = blockIdx.x * 256 + threadIdx.x;     // over 40960*96 8-float granules
    if (idx >= 40960 * 96) return;
    int mp = idx / 96, c = idx - mp * 96;
    int p = mp >> 11, b = mp & 2047;
    const float* src = X + ((size_t)b * 21 + 1 + p) * 768 + c * 8;
    float4 a = *(const float4*)src, bb = *(const float4*)(src + 4);
    *(uint4*)(g_xh + (size_t)mp * 768 + c * 8) = pack8h(a, bb);
}

// ---------------- prep 2: weights + smem-tiled w2 transpose (launch #2) ----------------
#define WG1  36864                // w1 granules  (384*768/8)
#define WGQ  73728                // per q/k/v    (768*768/8)
#define WB   1008                 // (36864+3*73728)/256 blocks
__global__ void kprepW(const float* __restrict__ w1, const float* __restrict__ wq,
                       const float* __restrict__ wk, const float* __restrict__ wv,
                       const float* __restrict__ w2) {
    __shared__ __half s[4 * 3456];
    int blk = blockIdx.x;
    if (blk < WB) {
        int idx = blk * 256 + threadIdx.x;
        const float* src; __half* dst; int i;
        if (idx < WG1)                   { i = idx;                src = w1; dst = g_w1h; }
        else if (idx < WG1 + WGQ)        { i = idx - WG1;          src = wq; dst = g_wqh; }
        else if (idx < WG1 + 2 * WGQ)    { i = idx - WG1 - WGQ;    src = wk; dst = g_wkh; }
        else                             { i = idx - WG1 - 2*WGQ;  src = wv; dst = g_wvh; }
        float4 a = *(const float4*)(src + (size_t)i * 8);
        float4 b = *(const float4*)(src + (size_t)i * 8 + 4);
        *(uint4*)(dst + (size_t)i * 8) = pack8h(a, b);
    } else {
        int o0 = (blk - WB) * 4;
        for (int e = threadIdx.x; e < 4 * 3456; e += 256) {
            int ol = e / 3456, j = e - ol * 3456;
            s[ol * 3456 + j] = __float2half(w2[(size_t)(o0 + ol) * 3456 + j]);
        }
        __syncthreads();
        for (int e = threadIdx.x; e < 4 * 3456; e += 256) {
            int ol = e / 3456, d = e - ol * 3456;
            int ic = d % 384, t = d / 384;
            g_w2th[(size_t)(o0 + ol) * 3456 + d] = s[ol * 3456 + ic * 9 + t];
        }
    }
}

// =====================================================================
// shared GEMM geometry: BM=128, BN=128, BK=64, 3-stage, 8 warps,
// warp tile 64x32, ldmatrix fragments, 2 CTAs/SM, one barrier per chunk
// =====================================================================
#define LDK  72
#define AS2  (128 * LDK)
#define ST2  (2 * AS2)
#define SMEMC (3 * ST2 * 2)       // 110592 bytes

// ---------------- generic GEMM (MODE 0: G1, MODE 2: QKV), BK=64, L=12 ----------------
template<int MODE>
__global__ __launch_bounds__(256, 2) void gemm_h(float* __restrict__ Cout) {
    constexpr int L = 12;                          // 768/64
    extern __shared__ __half smh[];
    const u32 sbase = smem_u32(smh);
    const int tid = threadIdx.x, wid = tid >> 5, lane = tid & 31;
    const int wm = wid >> 2, wn = wid & 3;
    const int lr = lane >> 2, lc = lane & 3;
    const int n0 = blockIdx.x * 128, m0 = blockIdx.y * 128;

    int which = 0, nw0 = n0;
    const __half* Bb;
    if (MODE == 2) {
        which = n0 / 768; nw0 = n0 - which * 768;
        Bb = (which == 0) ? g_wqh : (which == 1) ? g_wkh : g_wvh;
    } else {
        Bb = g_w1h;
    }
    const __half* Ab = (MODE == 0) ? g_xh : g_fh;

    const int arow_t = wm * 64 + ((lane >> 3) & 1) * 8 + (lane & 7);
    const int acol_t = (lane >> 4) * 8;
    const int brow_t = wn * 32 + (lane >> 4) * 8 + (lane & 7);
    const int bcol_t = ((lane >> 3) & 1) * 8;

    // A: 128x64 halves = 1024 16B slots -> 4/thread; B same
    u32 saoff[4]; const __half* aptr[4];
    u32 sboff[4]; const __half* bptr[4];
#pragma unroll
    for (int v = 0; v < 4; v++) {
        int idx = v * 256 + tid, r = idx >> 3, c8 = idx & 7;
        saoff[v] = (u32)(r * LDK + c8 * 8) * 2u;
        aptr[v] = Ab + (size_t)(m0 + r) * 768 + c8 * 8;
        sboff[v] = (u32)(AS2 + r * LDK + c8 * 8) * 2u;
        bptr[v] = Bb + (size_t)(nw0 + r) * 768 + c8 * 8;
    }

    auto load = [&](int c, int s) {
        u32 base = sbase + (u32)(s * ST2) * 2u;
#pragma unroll
        for (int v = 0; v < 4; v++) CPA(base + saoff[v], aptr[v] + (size_t)c * 64, 16u);
#pragma unroll
        for (int v = 0; v < 4; v++) CPA(base + sboff[v], bptr[v] + (size_t)c * 64, 16u);
        CPC();
    };

    float acc[4][4][4];
#pragma unroll
    for (int i = 0; i < 4; i++)
#pragma unroll
        for (int j = 0; j < 4; j++)
#pragma unroll
            for (int q = 0; q < 4; q++) acc[i][j][q] = 0.f;

    load(0, 0);
    load(1, 1);

    for (int c = 0; c < L; c++) {
        int s = c % 3;
        CPW(1);
        __syncthreads();
        if (c + 2 < L) load(c + 2, (c + 2) % 3); else CPC();

        const u32 sA = sbase + (u32)(s * ST2) * 2u;
        const u32 sB = sA + (u32)AS2 * 2u;
#pragma unroll
        for (int ks = 0; ks < 4; ks++) {
            u32 af[4][4];
#pragma unroll
            for (int mt = 0; mt < 4; mt++) {
                u32 addr = sA + (u32)((arow_t + mt * 16) * LDK + acol_t + ks * 16) * 2u;
                ldmx4(af[mt][0], af[mt][1], af[mt][2], af[mt][3], addr);
            }
            u32 bf[4][2];
#pragma unroll
            for (int np = 0; np < 2; np++) {
                u32 addr = sB + (u32)((brow_t + np * 16) * LDK + bcol_t + ks * 16) * 2u;
                ldmx4(bf[np * 2][0], bf[np * 2][1], bf[np * 2 + 1][0], bf[np * 2 + 1][1], addr);
            }
#pragma unroll
            for (int mt = 0; mt < 4; mt++)
#pragma unroll
                for (int nt = 0; nt < 4; nt++)
                    mma16(acc[mt][nt], af[mt], bf[nt]);
        }
    }

#pragma unroll
    for (int mt = 0; mt < 4; mt++) {
        int r0 = m0 + wm * 64 + mt * 16 + lr;
#pragma unroll
        for (int half = 0; half < 2; half++) {
            int m = r0 + half * 8;
#pragma unroll
            for (int nt = 0; nt < 4; nt++) {
                float v0 = acc[mt][nt][half * 2 + 0];
                float v1 = acc[mt][nt][half * 2 + 1];
                int colL = wn * 32 + nt * 8 + lc * 2;
                if (MODE == 0) {
                    __half2 h = __floats2half2_rn(gelu_f(v0), gelu_f(v1));
                    *(__half2*)(g_t1h + (size_t)m * 384 + n0 + colL) = h;
                } else {
                    int b = m >> 2, y = m & 3;
                    int n = nw0 + colL, nh = n >> 6, d = n & 63;
                    float* bp = Cout + (size_t)which * OUTSZ
                              + (((size_t)b * 12 + nh) * 20 + y * 5) * 64 + d;
                    float2 v = make_float2(v0, v1);
#pragma unroll
                    for (int xx = 0; xx < 5; xx++) *(float2*)(bp + xx * 64) = v;
                }
            }
        }
    }
}

// =====================================================================
// conv GEMM: BK=64, 3-stage (110.6KB smem, 2 CTAs/SM), single position
// per CTA, valid taps only, wave-balanced y-remap, gelu in epilogue
// (identical to R13 — proven 467us)
// =====================================================================
__global__ __launch_bounds__(256, 2) void gemm_conv() {
    extern __shared__ __half smh[];
    const u32 sbase = smem_u32(smh);
    const int tid = threadIdx.x, wid = tid >> 5, lane = tid & 31;
    const int wm = wid >> 2, wn = wid & 3;
    const int lr = lane >> 2, lc = lane & 3;
    const int n0 = blockIdx.x * 128;
    const int p = blockIdx.y % 20, bt = blockIdx.y / 20;
    const int m0 = p * 2048 + bt * 128;
    const int py = p / 5, px = p - py * 5;

    u64 spack = 0, wpack = 0; int ntap = 0;
#pragma unroll
    for (int dy = -1; dy <= 1; dy++) {
        int ny = py + dy; if ((unsigned)ny >= 4u) continue;
#pragma unroll
        for (int dx = -1; dx <= 1; dx++) {
            int nx = px + dx; if ((unsigned)nx >= 5u) continue;
            spack |= (u64)(ny * 5 + nx) << (5 * ntap);
            wpack |= (u64)((dy + 1) * 3 + (dx + 1)) << (4 * ntap);
            ntap++;
        }
    }
    const int L = ntap * 6;

    const int arow_t = wm * 64 + ((lane >> 3) & 1) * 8 + (lane & 7);
    const int acol_t = (lane >> 4) * 8;
    const int brow_t = wn * 32 + (lane >> 4) * 8 + (lane & 7);
    const int bcol_t = ((lane >> 3) & 1) * 8;

    u32 saoff[4]; int aoff[4];
    u32 sboff[4]; const __half* bptr[4];
#pragma unroll
    for (int v = 0; v < 4; v++) {
        int idx = v * 256 + tid, r = idx >> 3, c8 = idx & 7;
        saoff[v] = (u32)(r * LDK + c8 * 8) * 2u;
        aoff[v] = (bt * 128 + r) * 384 + c8 * 8;
        sboff[v] = (u32)(AS2 + r * LDK + c8 * 8) * 2u;
        bptr[v] = g_w2th + (size_t)(n0 + r) * 3456 + c8 * 8;
    }

    auto load = [&](int c, int s) {
        int ti = c / 6, cc = c - ti * 6, kk = cc * 64;
        int srcp = (int)((spack >> (5 * ti)) & 31u);
        int wt   = (int)((wpack >> (4 * ti)) & 15u);
        const __half* Asl = g_t1h + (size_t)srcp * (2048u * 384u) + kk;
        int boff = wt * 384 + kk;
        u32 base = sbase + (u32)(s * ST2) * 2u;
#pragma unroll
        for (int v = 0; v < 4; v++) CPA(base + saoff[v], Asl + aoff[v], 16u);
#pragma unroll
        for (int v = 0; v < 4; v++) CPA(base + sboff[v], bptr[v] + boff, 16u);
        CPC();
    };

    float acc[4][4][4];
#pragma unroll
    for (int i = 0; i < 4; i++)
#pragma unroll
        for (int j = 0; j < 4; j++)
#pragma unroll
            for (int q = 0; q < 4; q++) acc[i][j][q] = 0.f;

    load(0, 0);
    load(1, 1);

    for (int c = 0; c < L; c++) {
        int s = c % 3;
        CPW(1);
        __syncthreads();
        if (c + 2 < L) load(c + 2, (c + 2) % 3); else CPC();

        const u32 sA = sbase + (u32)(s * ST2) * 2u;
        const u32 sB = sA + (u32)AS2 * 2u;
#pragma unroll
        for (int ks = 0; ks < 4; ks++) {
            u32 af[4][4];
#pragma unroll
            for (int mt = 0; mt < 4; mt++) {
                u32 addr = sA + (u32)((arow_t + mt * 16) * LDK + acol_t + ks * 16) * 2u;
                ldmx4(af[mt][0], af[mt][1], af[mt][2], af[mt][3], addr);
            }
            u32 bf[4][2];
#pragma unroll
            for (int np = 0; np < 2; np++) {
                u32 addr = sB + (u32)((brow_t + np * 16) * LDK + bcol_t + ks * 16) * 2u;
                ldmx4(bf[np * 2][0], bf[np * 2][1], bf[np * 2 + 1][0], bf[np * 2 + 1][1], addr);
            }
#pragma unroll
            for (int mt = 0; mt < 4; mt++)
#pragma unroll
                for (int nt = 0; nt < 4; nt++)
                    mma16(acc[mt][nt], af[mt], bf[nt]);
        }
    }

    // epilogue: gelu fused (kfilter is pure bandwidth)
#pragma unroll
    for (int mt = 0; mt < 4; mt++) {
        int r0 = m0 + wm * 64 + mt * 16 + lr;
#pragma unroll
        for (int half = 0; half < 2; half++) {
            int m = r0 + half * 8;
#pragma unroll
            for (int nt = 0; nt < 4; nt++) {
                float v0 = gelu_f(acc[mt][nt][half * 2 + 0]);
                float v1 = gelu_f(acc[mt][nt][half * 2 + 1]);
                int colL = wn * 32 + nt * 8 + lc * 2;
                __half2 h = __floats2half2_rn(v0, v1);
                *(__half2*)(g_t2h + (size_t)m * 768 + n0 + colL) = h;
            }
        }
    }
}

// ---------------- filter (launch #5): pure-bandwidth sums + analytic low-pass ----------------
__global__ void kfilter() {
    int idx = blockIdx.x * 256 + threadIdx.x;     // over 2048*192 (4 channels each)
    if (idx >= 2048 * 192) return;
    int b = idx / 192, oq = idx - b * 192;
    const __half* src = g_t2h + (size_t)b * 768 + oq * 4;
    float ry[4][4];
#pragma unroll
    for (int y = 0; y < 4; y++) {
        float a0 = 0.f, a1 = 0.f, a2 = 0.f, a3 = 0.f;
#pragma unroll
        for (int x = 0; x < 5; x++) {
            const __half2* pp = (const __half2*)(src + (size_t)(y * 5 + x) * 2048u * 768u);
            float2 v01 = __half22float2(pp[0]);
            float2 v23 = __half22float2(pp[1]);
            a0 += v01.x; a1 += v01.y; a2 += v23.x; a3 += v23.y;
        }
        ry[y][0] = a0; ry[y][1] = a1; ry[y][2] = a2; ry[y][3] = a3;
    }
    __half o[4][4];
#pragma unroll
    for (int j = 0; j < 4; j++) {
        float S  = ry[0][j] + ry[1][j] + ry[2][j] + ry[3][j];
        float A  = ry[0][j] - ry[2][j];
        float Bv = ry[1][j] - ry[3][j];
        o[0][j] = __float2half(sqrtf((S + A) * (S + A) + Bv * Bv) * 0.05f);
        o[1][j] = __float2half(sqrtf((S + Bv) * (S + Bv) + A * A) * 0.05f);
        o[2][j] = __float2half(sqrtf((S - A) * (S - A) + Bv * Bv) * 0.05f);
        o[3][j] = __float2half(sqrtf((S - Bv) * (S - Bv) + A * A) * 0.05f);
    }
    __half* dst = g_fh + (size_t)b * 4 * 768 + oq * 4;
#pragma unroll
    for (int y = 0; y < 4; y++) {
        uint2 u;
        __half2 h0; h0.x = o[y][0]; h0.y = o[y][1];
        __half2 h1; h1.x = o[y][2]; h1.y = o[y][3];
        u.x = *(const unsigned*)&h0; u.y = *(const unsigned*)&h1;
        *(uint2*)(dst + (size_t)y * 768) = u;
    }
}

// ---------------- launch ----------------
extern "C" void kernel_launch(void* const* d_in, const int* in_sizes, int n_in,
                              void* d_out, int out_size) {
    const float* x  = (const float*)d_in[0];
    const float* w1 = (const float*)d_in[1];
    const float* w2 = (const float*)d_in[2];
    const float* wq = (const float*)d_in[3];
    const float* wk = (const float*)d_in[4];
    const float* wv = (const float*)d_in[5];
    float* out = (float*)d_out;

    cudaFuncSetAttribute(gemm_h<0>, cudaFuncAttributeMaxDynamicSharedMemorySize, SMEMC);
    cudaFuncSetAttribute(gemm_h<2>, cudaFuncAttributeMaxDynamicSharedMemorySize, SMEMC);
    cudaFuncSetAttribute(gemm_conv, cudaFuncAttributeMaxDynamicSharedMemorySize, SMEMC);

    kprepX<<<15360, 256>>>(x);                                // #1: X reorder
    kprepW<<<WB + 192, 256>>>(w1, wq, wk, wv, w2);            // #2: weights + w2t transpose
    gemm_h<0><<<dim3(3, 320), 256, SMEMC>>>(nullptr);         // #3: t1 = gelu(X@W1^T), BK=64
    gemm_conv<<<dim3(6, 320), 256, SMEMC>>>();                // #4: conv3x3 + gelu (ncu target)
    kfilter<<<(2048 * 192 + 255) / 256, 256>>>();             // #5: sums + analytic low-pass
    gemm_h<2><<<dim3(18, 64), 256, SMEMC>>>(out);             // #6: QKV + replicated scatter, BK=64
}